// round 12
// baseline (speedup 1.0000x reference)
#include <cuda_runtime.h>
#include <cuda_fp16.h>
#include <stdint.h>
#include <math.h>

#define BATCH 2048
#define TSTEPS 25
#define MROWS (TSTEPS * BATCH)       // 51200
#define D0 100
#define D1 128
#define D2 256
#define D3 512
#define D4 1024
#define D5 784
#define D5P 832

#define BETA 0.95f
#define THRESH 1.0f
#define H2SCALE 2048.0f
#define H2INV (1.0f / 2048.0f)

// ------------------------- persistent device state -------------------------
__device__ float g_cur1[BATCH * D1];

__device__ __half g_spkA[(size_t)MROWS * D4];
__device__ __half g_spkB[(size_t)MROWS * D4];
__device__ float  g_cur[(size_t)MROWS * D4];

#define W2OFF 0
#define W3OFF (W2OFF + D2*D1)
#define W4OFF (W3OFF + D3*D2)
#define W5OFF (W4OFF + D4*D3)
#define WTOTAL (W5OFF + D5P*D4)
__device__ __half g_h1[WTOTAL];
__device__ __half g_h2[WTOTAL];

// ------------------------------ utilities ----------------------------------
__global__ void split_w_kernel(const float* __restrict__ W, int N, int K,
                               int Npad, int off)
{
    int stride = gridDim.x * blockDim.x;
    int total = Npad * K;
    int nk = N * K;
    for (int i = blockIdx.x * blockDim.x + threadIdx.x; i < total; i += stride) {
        float w = 0.0f;
        if (i < nk) { w = W[i]; }
        __half h1 = __float2half(w);
        float r1 = w - __half2float(h1);
        g_h1[off + i] = h1;
        g_h2[off + i] = __float2half(r1 * H2SCALE);
    }
}

__global__ void lif1_scan_kernel()
{
    int idx = blockIdx.x * blockDim.x + threadIdx.x;
    if (idx < BATCH * D1) {
        float cur = g_cur1[idx];
        float mem = 0.0f;
#pragma unroll
        for (int t = 0; t < TSTEPS; t++) {
            float rst = (mem > THRESH) ? 1.0f : 0.0f;
            mem = BETA * mem + cur - rst * THRESH;
            float sp = (mem > THRESH) ? 1.0f : 0.0f;
            g_spkA[(size_t)t * (BATCH * D1) + idx] = __float2half(sp);
        }
    }
}

// LIF scan, 2 elements per thread: g_cur fp32 -> spikes fp16
__global__ void lif_scan_kernel(int sbuf, int N)
{
    __half* spk = (sbuf == 0) ? g_spkA : g_spkB;
    int idx = (blockIdx.x * blockDim.x + threadIdx.x) * 2;
    size_t stride = (size_t)BATCH * N;
    float m0 = 0.0f;
    float m1 = 0.0f;
#pragma unroll
    for (int t = 0; t < TSTEPS; t++) {
        float2 cur = *reinterpret_cast<const float2*>(&g_cur[(size_t)t * stride + idx]);
        float r0 = (m0 > THRESH) ? 1.0f : 0.0f;
        float r1 = (m1 > THRESH) ? 1.0f : 0.0f;
        m0 = BETA * m0 + cur.x - r0 * THRESH;
        m1 = BETA * m1 + cur.y - r1 * THRESH;
        __half2 sp;
        sp.x = __float2half((m0 > THRESH) ? 1.0f : 0.0f);
        sp.y = __float2half((m1 > THRESH) ? 1.0f : 0.0f);
        *reinterpret_cast<__half2*>(&spk[(size_t)t * stride + idx]) = sp;
    }
}

__global__ void lif5_scan_kernel(float* __restrict__ out_spk,
                                 float* __restrict__ out_mem)
{
    int idx = blockIdx.x * blockDim.x + threadIdx.x;
    int b = idx / D5;
    int n = idx - b * D5;
    size_t cbase = (size_t)b * D5P + n;
    size_t cstep = (size_t)BATCH * D5P;
    size_t ostep = (size_t)BATCH * D5;
    float mem = 0.0f;
#pragma unroll
    for (int t = 0; t < TSTEPS; t++) {
        float cur = g_cur[cbase + (size_t)t * cstep];
        float rst = (mem > THRESH) ? 1.0f : 0.0f;
        mem = BETA * mem + cur - rst * THRESH;
        float sp = (mem > THRESH) ? 1.0f : 0.0f;
        out_spk[(size_t)t * ostep + idx] = sp;
        out_mem[(size_t)t * ostep + idx] = tanhf(mem);
    }
}

// ----------------- layer-1 fp32 GEMM (runs once per launch) ----------------
__global__ __launch_bounds__(256)
void cur1_kernel(const float* __restrict__ A, const float* __restrict__ W,
                 const float* __restrict__ bias)
{
    const int N = D1;
    const int K = D0;
    __shared__ float As[16][128];
    __shared__ float Ws[16][64];

    int tid = threadIdx.x;
    int tx = tid & 15;
    int ty = tid >> 4;
    int m0 = blockIdx.y * 128;
    int n0 = blockIdx.x * 64;

    float acc[8][4];
#pragma unroll
    for (int i = 0; i < 8; i++) {
#pragma unroll
        for (int j = 0; j < 4; j++) { acc[i][j] = 0.0f; }
    }

    for (int k0 = 0; k0 < K; k0 += 16) {
#pragma unroll
        for (int it = 0; it < 2; it++) {
            int f4 = it * 256 + tid;
            int row = f4 >> 2;
            int q = f4 & 3;
            int gk = k0 + q * 4;
            float4 v = make_float4(0.f, 0.f, 0.f, 0.f);
            if (gk < K) {
                v = *reinterpret_cast<const float4*>(&A[(size_t)(m0 + row) * K + gk]);
            }
            As[q*4+0][row] = v.x;
            As[q*4+1][row] = v.y;
            As[q*4+2][row] = v.z;
            As[q*4+3][row] = v.w;
        }
        {
            int row = tid >> 2;
            int q = tid & 3;
            int gk = k0 + q * 4;
            float4 v = make_float4(0.f, 0.f, 0.f, 0.f);
            if (gk < K) {
                v = *reinterpret_cast<const float4*>(&W[(size_t)(n0 + row) * K + gk]);
            }
            Ws[q*4+0][row] = v.x;
            Ws[q*4+1][row] = v.y;
            Ws[q*4+2][row] = v.z;
            Ws[q*4+3][row] = v.w;
        }
        __syncthreads();
#pragma unroll
        for (int kk = 0; kk < 16; kk++) {
            float av[8];
            float wv[4];
#pragma unroll
            for (int i = 0; i < 8; i++) { av[i] = As[kk][ty * 8 + i]; }
#pragma unroll
            for (int j = 0; j < 4; j++) { wv[j] = Ws[kk][tx * 4 + j]; }
#pragma unroll
            for (int i = 0; i < 8; i++) {
#pragma unroll
                for (int j = 0; j < 4; j++) {
                    acc[i][j] = fmaf(av[i], wv[j], acc[i][j]);
                }
            }
        }
        __syncthreads();
    }

#pragma unroll
    for (int i = 0; i < 8; i++) {
        int gm = m0 + ty * 8 + i;
#pragma unroll
        for (int j = 0; j < 4; j++) {
            int gn = n0 + tx * 4 + j;
            g_cur1[(size_t)gm * N + gn] = fmaxf(acc[i][j] + bias[gn], 0.0f);
        }
    }
}

// ------------------- tensor-core GEMM (mma.sync, fp16 2-term) --------------
// BM=128, BN=64, BK=64; 8 warps as 4(M) x 2(N); warp tile 32x32; 3 stages.
#define SWZ(x) ((x) ^ (((x) >> 3) & 0x70))
#define ABUF_BYTES 16384
#define BBUF_BYTES 8192
#define STAGE_BYTES 32768
#define NSTAGES 3

__device__ __forceinline__ void cp16(uint32_t s, const void* g)
{
    asm volatile("cp.async.cg.shared.global [%0], [%1], 16;" :: "r"(s), "l"(g));
}

__device__ __forceinline__ void ldsm4(uint32_t* r, uint32_t s)
{
    asm volatile("ldmatrix.sync.aligned.m8n8.x4.shared.b16 {%0,%1,%2,%3}, [%4];"
                 : "=r"(r[0]), "=r"(r[1]), "=r"(r[2]), "=r"(r[3]) : "r"(s));
}

__device__ __forceinline__ void mma_f16(float* c, const uint32_t* a, const uint32_t* b)
{
    asm volatile("mma.sync.aligned.m16n8k16.row.col.f32.f16.f16.f32 "
                 "{%0,%1,%2,%3}, {%4,%5,%6,%7}, {%8,%9}, {%0,%1,%2,%3};"
                 : "+f"(c[0]), "+f"(c[1]), "+f"(c[2]), "+f"(c[3])
                 : "r"(a[0]), "r"(a[1]), "r"(a[2]), "r"(a[3]),
                   "r"(b[0]), "r"(b[1]));
}

__device__ __forceinline__ void load_stage(uint32_t sbase,
                                           const __half* A, const __half* P1,
                                           const __half* P2,
                                           int m0, int n0, int k0, int K, int tid)
{
    // A: 128 rows x 64 halfs (128B/row) = 1024 cp16
#pragma unroll
    for (int it = 0; it < 4; it++) {
        int idx = it * 256 + tid;
        int row = idx >> 3;
        int c8 = idx & 7;
        cp16(sbase + SWZ(row * 128 + c8 * 16),
             A + (size_t)(m0 + row) * K + k0 + c8 * 8);
    }
    // B1, B2: 64 rows x 64 halfs each = 512 cp16 each
#pragma unroll
    for (int it = 0; it < 2; it++) {
        int idx = it * 256 + tid;
        int row = idx >> 3;
        int c8 = idx & 7;
        uint32_t d = SWZ(row * 128 + c8 * 16);
        size_t goff = (size_t)(n0 + row) * K + k0 + c8 * 8;
        cp16(sbase + ABUF_BYTES + d, P1 + goff);
        cp16(sbase + ABUF_BYTES + BBUF_BYTES + d, P2 + goff);
    }
}

// C[M=51200, N] = A[M,K] @ (h1 + h2/2048)[N,K]^T ; relu(+bias) -> g_cur
__global__ __launch_bounds__(256)
void gemm_kernel(int abuf, int woff, const float* __restrict__ bias,
                 int N, int N_real, int K)
{
    extern __shared__ __align__(128) char smem_raw[];
    const uint32_t smem = (uint32_t)__cvta_generic_to_shared(smem_raw);

    const __half* __restrict__ A  = (abuf == 0) ? g_spkA : g_spkB;
    const __half* __restrict__ P1 = g_h1 + woff;
    const __half* __restrict__ P2 = g_h2 + woff;

    const int tid = threadIdx.x;
    const int lane = tid & 31;
    const int warp = tid >> 5;
    const int wm = warp >> 1;           // 0..3  (M direction, 32 rows each)
    const int wn = warp & 1;            // 0..1  (N direction, 32 cols each)
    const int m0 = blockIdx.y * 128;
    const int n0 = blockIdx.x * 64;

    float asum[2][4][4];
#pragma unroll
    for (int i = 0; i < 2; i++) {
#pragma unroll
        for (int j = 0; j < 4; j++) {
#pragma unroll
            for (int k = 0; k < 4; k++) { asum[i][j][k] = 0.0f; }
        }
    }

    const int nk = K >> 6;

    // prologue: stages 0,1
    load_stage(smem, A, P1, P2, m0, n0, 0, K, tid);
    asm volatile("cp.async.commit_group;");
    if (nk > 1) {
        load_stage(smem + STAGE_BYTES, A, P1, P2, m0, n0, 64, K, tid);
        asm volatile("cp.async.commit_group;");
    }

    const int arow = wm * 32 + (lane & 15);
    const int akc = lane >> 4;
    const int bq = lane >> 3;
    const int brow0 = wn * 32 + ((bq >> 1) << 3) + (lane & 7);
    const int bkc = bq & 1;

    for (int i = 0; i < nk; i++) {
        if (i + 2 < nk) {
            load_stage(smem + ((i + 2) % NSTAGES) * STAGE_BYTES,
                       A, P1, P2, m0, n0, (i + 2) * 64, K, tid);
            asm volatile("cp.async.commit_group;");
        }
        int allow = nk - 1 - i;
        if (allow > 2) { allow = 2; }
        if (allow == 2) {
            asm volatile("cp.async.wait_group 2;");
        } else if (allow == 1) {
            asm volatile("cp.async.wait_group 1;");
        } else {
            asm volatile("cp.async.wait_group 0;");
        }
        __syncthreads();

        float accA[2][4][4];
        float accB[2][4][4];
#pragma unroll
        for (int ii = 0; ii < 2; ii++) {
#pragma unroll
            for (int jj = 0; jj < 4; jj++) {
#pragma unroll
                for (int kk2 = 0; kk2 < 4; kk2++) {
                    accA[ii][jj][kk2] = 0.0f;
                    accB[ii][jj][kk2] = 0.0f;
                }
            }
        }

        uint32_t base = smem + (i % NSTAGES) * STAGE_BYTES;
        uint32_t sA = base;
        uint32_t s1 = base + ABUF_BYTES;
        uint32_t s2 = base + ABUF_BYTES + BBUF_BYTES;
#pragma unroll
        for (int kk = 0; kk < 4; kk++) {
            uint32_t af[2][4];
            uint32_t b1[8];
            uint32_t b2[8];
#pragma unroll
            for (int mi = 0; mi < 2; mi++) {
                ldsm4(af[mi], sA + SWZ((arow + mi * 16) * 128 + (kk * 2 + akc) * 16));
            }
            ldsm4(b1,     s1 + SWZ(brow0 * 128 + (kk * 2 + bkc) * 16));
            ldsm4(b1 + 4, s1 + SWZ((brow0 + 16) * 128 + (kk * 2 + bkc) * 16));
            ldsm4(b2,     s2 + SWZ(brow0 * 128 + (kk * 2 + bkc) * 16));
            ldsm4(b2 + 4, s2 + SWZ((brow0 + 16) * 128 + (kk * 2 + bkc) * 16));
#pragma unroll
            for (int mi = 0; mi < 2; mi++) {
#pragma unroll
                for (int nf = 0; nf < 4; nf++) {
                    mma_f16(accA[mi][nf], af[mi], b1 + 2 * nf);
                    mma_f16(accB[mi][nf], af[mi], b2 + 2 * nf);
                }
            }
        }

        // fold with exact fp32 RN ops; h2 term de-scaled
#pragma unroll
        for (int ii = 0; ii < 2; ii++) {
#pragma unroll
            for (int jj = 0; jj < 4; jj++) {
#pragma unroll
                for (int kk2 = 0; kk2 < 4; kk2++) {
                    asum[ii][jj][kk2] += fmaf(accB[ii][jj][kk2], H2INV,
                                              accA[ii][jj][kk2]);
                }
            }
        }
        __syncthreads();
    }

    // epilogue: relu(asum + bias) -> g_cur
#pragma unroll
    for (int mi = 0; mi < 2; mi++) {
        int rbase = m0 + wm * 32 + mi * 16 + (lane >> 2);
#pragma unroll
        for (int nf = 0; nf < 4; nf++) {
            int col = n0 + wn * 32 + nf * 8 + (lane & 3) * 2;
            float bia0 = (col < N_real) ? bias[col] : 0.0f;
            float bia1 = (col + 1 < N_real) ? bias[col + 1] : 0.0f;
#pragma unroll
            for (int h = 0; h < 2; h++) {
                int row = rbase + h * 8;
                float cu0 = fmaxf(asum[mi][nf][h * 2 + 0] + bia0, 0.0f);
                float cu1 = fmaxf(asum[mi][nf][h * 2 + 1] + bia1, 0.0f);
                *reinterpret_cast<float2*>(&g_cur[(size_t)row * N + col]) =
                    make_float2(cu0, cu1);
            }
        }
    }
}

// ------------------------------ host launcher ------------------------------
extern "C" void kernel_launch(void* const* d_in, const int* in_sizes, int n_in,
                              void* d_out, int out_size)
{
    const float* x  = (const float*)d_in[0];
    const float* W1 = (const float*)d_in[1];
    const float* b1 = (const float*)d_in[2];
    const float* W2 = (const float*)d_in[3];
    const float* b2 = (const float*)d_in[4];
    const float* W3 = (const float*)d_in[5];
    const float* b3 = (const float*)d_in[6];
    const float* W4 = (const float*)d_in[7];
    const float* b4 = (const float*)d_in[8];
    const float* W5 = (const float*)d_in[9];
    const float* b5 = (const float*)d_in[10];

    float* out = (float*)d_out;
    float* out_spk = out;
    float* out_mem = out + (size_t)TSTEPS * BATCH * D5;

    static int smem_set = 0;
    if (smem_set == 0) {
        cudaFuncSetAttribute(gemm_kernel,
                             cudaFuncAttributeMaxDynamicSharedMemorySize,
                             NSTAGES * STAGE_BYTES);
        smem_set = 1;
    }

    split_w_kernel<<<128, 256>>>(W2, D2, D1, D2, W2OFF);
    split_w_kernel<<<256, 256>>>(W3, D3, D2, D3, W3OFF);
    split_w_kernel<<<512, 256>>>(W4, D4, D3, D4, W4OFF);
    split_w_kernel<<<896, 256>>>(W5, D5, D4, D5P, W5OFF);

    cur1_kernel<<<dim3(2, 16), 256>>>(x, W1, b1);
    lif1_scan_kernel<<<(BATCH * D1) / 256, 256>>>();

    const int MB = MROWS / 128;   // 400

    gemm_kernel<<<dim3(D2 / 64, MB), 256, NSTAGES * STAGE_BYTES>>>(
        0, W2OFF, b2, D2, D2, D1);
    lif_scan_kernel<<<(BATCH * D2) / 512, 256>>>(1, D2);

    gemm_kernel<<<dim3(D3 / 64, MB), 256, NSTAGES * STAGE_BYTES>>>(
        1, W3OFF, b3, D3, D3, D2);
    lif_scan_kernel<<<(BATCH * D3) / 512, 256>>>(0, D3);

    gemm_kernel<<<dim3(D4 / 64, MB), 256, NSTAGES * STAGE_BYTES>>>(
        0, W4OFF, b4, D4, D4, D3);
    lif_scan_kernel<<<(BATCH * D4) / 512, 256>>>(1, D4);

    gemm_kernel<<<dim3(D5P / 64, MB), 256, NSTAGES * STAGE_BYTES>>>(
        1, W5OFF, b5, D5P, D5, D4);
    lif5_scan_kernel<<<(BATCH * D5) / 256, 256>>>(out_spk, out_mem);
}

// round 13
// speedup vs baseline: 1.1274x; 1.1274x over previous
#include <cuda_runtime.h>
#include <cuda_fp16.h>
#include <stdint.h>
#include <math.h>

#define BATCH 2048
#define TSTEPS 25
#define MROWS (TSTEPS * BATCH)       // 51200
#define D0 100
#define D1 128
#define D2 256
#define D3 512
#define D4 1024
#define D5 784
#define D5P 832

#define BETA 0.95f
#define THRESH 1.0f
#define H2SCALE 2048.0f
#define H2INV (1.0f / 2048.0f)

// ------------------------- persistent device state -------------------------
__device__ float g_cur1[BATCH * D1];

__device__ __half g_spkA[(size_t)MROWS * D4];
__device__ __half g_spkB[(size_t)MROWS * D4];
__device__ float  g_cur[(size_t)MROWS * D4];

#define W2OFF 0
#define W3OFF (W2OFF + D2*D1)
#define W4OFF (W3OFF + D3*D2)
#define W5OFF (W4OFF + D4*D3)
#define WTOTAL (W5OFF + D5P*D4)
__device__ __half g_h1[WTOTAL];
__device__ __half g_h2[WTOTAL];

// ------------------------------ utilities ----------------------------------
__global__ void split_w_kernel(const float* __restrict__ W, int N, int K,
                               int Npad, int off)
{
    int stride = gridDim.x * blockDim.x;
    int total = Npad * K;
    int nk = N * K;
    for (int i = blockIdx.x * blockDim.x + threadIdx.x; i < total; i += stride) {
        float w = 0.0f;
        if (i < nk) { w = W[i]; }
        __half h1 = __float2half(w);
        float r1 = w - __half2float(h1);
        g_h1[off + i] = h1;
        g_h2[off + i] = __float2half(r1 * H2SCALE);
    }
}

__global__ void lif1_scan_kernel()
{
    int idx = blockIdx.x * blockDim.x + threadIdx.x;
    if (idx < BATCH * D1) {
        float cur = g_cur1[idx];
        float mem = 0.0f;
#pragma unroll
        for (int t = 0; t < TSTEPS; t++) {
            float rst = (mem > THRESH) ? 1.0f : 0.0f;
            mem = BETA * mem + cur - rst * THRESH;
            float sp = (mem > THRESH) ? 1.0f : 0.0f;
            g_spkA[(size_t)t * (BATCH * D1) + idx] = __float2half(sp);
        }
    }
}

// LIF scan, 4 elements per thread: g_cur fp32 -> spikes fp16
__global__ void lif_scan_kernel(int sbuf, int N)
{
    __half* spk = (sbuf == 0) ? g_spkA : g_spkB;
    int idx = (blockIdx.x * blockDim.x + threadIdx.x) * 4;
    size_t stride = (size_t)BATCH * N;
    float m0 = 0.0f;
    float m1 = 0.0f;
    float m2 = 0.0f;
    float m3 = 0.0f;
#pragma unroll
    for (int t = 0; t < TSTEPS; t++) {
        float4 cur = *reinterpret_cast<const float4*>(&g_cur[(size_t)t * stride + idx]);
        float r0 = (m0 > THRESH) ? 1.0f : 0.0f;
        float r1 = (m1 > THRESH) ? 1.0f : 0.0f;
        float r2 = (m2 > THRESH) ? 1.0f : 0.0f;
        float r3 = (m3 > THRESH) ? 1.0f : 0.0f;
        m0 = BETA * m0 + cur.x - r0 * THRESH;
        m1 = BETA * m1 + cur.y - r1 * THRESH;
        m2 = BETA * m2 + cur.z - r2 * THRESH;
        m3 = BETA * m3 + cur.w - r3 * THRESH;
        __half2 p0;
        __half2 p1;
        p0.x = __float2half((m0 > THRESH) ? 1.0f : 0.0f);
        p0.y = __float2half((m1 > THRESH) ? 1.0f : 0.0f);
        p1.x = __float2half((m2 > THRESH) ? 1.0f : 0.0f);
        p1.y = __float2half((m3 > THRESH) ? 1.0f : 0.0f);
        uint2 pk;
        pk.x = *reinterpret_cast<uint32_t*>(&p0);
        pk.y = *reinterpret_cast<uint32_t*>(&p1);
        *reinterpret_cast<uint2*>(&spk[(size_t)t * stride + idx]) = pk;
    }
}

// layer-5 scan, 4 elements per thread (784 % 4 == 0 keeps quads in-row)
__global__ void lif5_scan_kernel(float* __restrict__ out_spk,
                                 float* __restrict__ out_mem)
{
    int idx = (blockIdx.x * blockDim.x + threadIdx.x) * 4;
    int b = idx / D5;
    int n = idx - b * D5;
    size_t cbase = (size_t)b * D5P + n;
    size_t cstep = (size_t)BATCH * D5P;
    size_t ostep = (size_t)BATCH * D5;
    float m0 = 0.0f;
    float m1 = 0.0f;
    float m2 = 0.0f;
    float m3 = 0.0f;
#pragma unroll
    for (int t = 0; t < TSTEPS; t++) {
        float4 cur = *reinterpret_cast<const float4*>(&g_cur[cbase + (size_t)t * cstep]);
        float r0 = (m0 > THRESH) ? 1.0f : 0.0f;
        float r1 = (m1 > THRESH) ? 1.0f : 0.0f;
        float r2 = (m2 > THRESH) ? 1.0f : 0.0f;
        float r3 = (m3 > THRESH) ? 1.0f : 0.0f;
        m0 = BETA * m0 + cur.x - r0 * THRESH;
        m1 = BETA * m1 + cur.y - r1 * THRESH;
        m2 = BETA * m2 + cur.z - r2 * THRESH;
        m3 = BETA * m3 + cur.w - r3 * THRESH;
        float4 sp;
        sp.x = (m0 > THRESH) ? 1.0f : 0.0f;
        sp.y = (m1 > THRESH) ? 1.0f : 0.0f;
        sp.z = (m2 > THRESH) ? 1.0f : 0.0f;
        sp.w = (m3 > THRESH) ? 1.0f : 0.0f;
        *reinterpret_cast<float4*>(&out_spk[(size_t)t * ostep + idx]) = sp;
        float4 tm;
        tm.x = tanhf(m0);
        tm.y = tanhf(m1);
        tm.z = tanhf(m2);
        tm.w = tanhf(m3);
        *reinterpret_cast<float4*>(&out_mem[(size_t)t * ostep + idx]) = tm;
    }
}

// ----------------- layer-1 fp32 GEMM (runs once per launch) ----------------
__global__ __launch_bounds__(256)
void cur1_kernel(const float* __restrict__ A, const float* __restrict__ W,
                 const float* __restrict__ bias)
{
    const int N = D1;
    const int K = D0;
    __shared__ float As[16][128];
    __shared__ float Ws[16][64];

    int tid = threadIdx.x;
    int tx = tid & 15;
    int ty = tid >> 4;
    int m0 = blockIdx.y * 128;
    int n0 = blockIdx.x * 64;

    float acc[8][4];
#pragma unroll
    for (int i = 0; i < 8; i++) {
#pragma unroll
        for (int j = 0; j < 4; j++) { acc[i][j] = 0.0f; }
    }

    for (int k0 = 0; k0 < K; k0 += 16) {
#pragma unroll
        for (int it = 0; it < 2; it++) {
            int f4 = it * 256 + tid;
            int row = f4 >> 2;
            int q = f4 & 3;
            int gk = k0 + q * 4;
            float4 v = make_float4(0.f, 0.f, 0.f, 0.f);
            if (gk < K) {
                v = *reinterpret_cast<const float4*>(&A[(size_t)(m0 + row) * K + gk]);
            }
            As[q*4+0][row] = v.x;
            As[q*4+1][row] = v.y;
            As[q*4+2][row] = v.z;
            As[q*4+3][row] = v.w;
        }
        {
            int row = tid >> 2;
            int q = tid & 3;
            int gk = k0 + q * 4;
            float4 v = make_float4(0.f, 0.f, 0.f, 0.f);
            if (gk < K) {
                v = *reinterpret_cast<const float4*>(&W[(size_t)(n0 + row) * K + gk]);
            }
            Ws[q*4+0][row] = v.x;
            Ws[q*4+1][row] = v.y;
            Ws[q*4+2][row] = v.z;
            Ws[q*4+3][row] = v.w;
        }
        __syncthreads();
#pragma unroll
        for (int kk = 0; kk < 16; kk++) {
            float av[8];
            float wv[4];
#pragma unroll
            for (int i = 0; i < 8; i++) { av[i] = As[kk][ty * 8 + i]; }
#pragma unroll
            for (int j = 0; j < 4; j++) { wv[j] = Ws[kk][tx * 4 + j]; }
#pragma unroll
            for (int i = 0; i < 8; i++) {
#pragma unroll
                for (int j = 0; j < 4; j++) {
                    acc[i][j] = fmaf(av[i], wv[j], acc[i][j]);
                }
            }
        }
        __syncthreads();
    }

#pragma unroll
    for (int i = 0; i < 8; i++) {
        int gm = m0 + ty * 8 + i;
#pragma unroll
        for (int j = 0; j < 4; j++) {
            int gn = n0 + tx * 4 + j;
            g_cur1[(size_t)gm * N + gn] = fmaxf(acc[i][j] + bias[gn], 0.0f);
        }
    }
}

// ------------------- tensor-core GEMM (mma.sync, fp16 2-term) --------------
// BM=64, BN=64, BK=64 (R11-proven); 3-stage cp.async pipeline.
#define SWZ(x) ((x) ^ (((x) >> 3) & 0x70))
#define STAGE_BYTES 24576
#define NSTAGES 3

__device__ __forceinline__ void cp16(uint32_t s, const void* g)
{
    asm volatile("cp.async.cg.shared.global [%0], [%1], 16;" :: "r"(s), "l"(g));
}

__device__ __forceinline__ void ldsm4(uint32_t* r, uint32_t s)
{
    asm volatile("ldmatrix.sync.aligned.m8n8.x4.shared.b16 {%0,%1,%2,%3}, [%4];"
                 : "=r"(r[0]), "=r"(r[1]), "=r"(r[2]), "=r"(r[3]) : "r"(s));
}

__device__ __forceinline__ void mma_f16(float* c, const uint32_t* a, const uint32_t* b)
{
    asm volatile("mma.sync.aligned.m16n8k16.row.col.f32.f16.f16.f32 "
                 "{%0,%1,%2,%3}, {%4,%5,%6,%7}, {%8,%9}, {%0,%1,%2,%3};"
                 : "+f"(c[0]), "+f"(c[1]), "+f"(c[2]), "+f"(c[3])
                 : "r"(a[0]), "r"(a[1]), "r"(a[2]), "r"(a[3]),
                   "r"(b[0]), "r"(b[1]));
}

__device__ __forceinline__ void load_stage(uint32_t sbase,
                                           const __half* A, const __half* P1,
                                           const __half* P2,
                                           int m0, int n0, int k0, int K, int tid)
{
    int crow = tid >> 3;
    int ccol = tid & 7;
#pragma unroll
    for (int it = 0; it < 2; it++) {
        int row = it * 32 + crow;
        uint32_t d = SWZ(row * 128 + ccol * 16);
        cp16(sbase + d,         A  + (size_t)(m0 + row) * K + k0 + ccol * 8);
        cp16(sbase + 8192 + d,  P1 + (size_t)(n0 + row) * K + k0 + ccol * 8);
        cp16(sbase + 16384 + d, P2 + (size_t)(n0 + row) * K + k0 + ccol * 8);
    }
}

// C[M=51200, N] = A[M,K] @ (h1 + h2/2048)[N,K]^T ; relu(+bias) -> g_cur
__global__ __launch_bounds__(256)
void gemm_kernel(int abuf, int woff, const float* __restrict__ bias,
                 int N, int N_real, int K)
{
    extern __shared__ __align__(128) char smem_raw[];
    const uint32_t smem = (uint32_t)__cvta_generic_to_shared(smem_raw);

    const __half* __restrict__ A  = (abuf == 0) ? g_spkA : g_spkB;
    const __half* __restrict__ P1 = g_h1 + woff;
    const __half* __restrict__ P2 = g_h2 + woff;

    const int tid = threadIdx.x;
    const int lane = tid & 31;
    const int warp = tid >> 5;
    const int wm = warp >> 2;
    const int wn = warp & 3;
    const int m0 = blockIdx.y * 64;
    const int n0 = blockIdx.x * 64;

    float asum[2][2][4];
#pragma unroll
    for (int i = 0; i < 2; i++) {
#pragma unroll
        for (int j = 0; j < 2; j++) {
#pragma unroll
            for (int k = 0; k < 4; k++) { asum[i][j][k] = 0.0f; }
        }
    }

    const int nk = K >> 6;

    // prologue: stages 0,1
    load_stage(smem, A, P1, P2, m0, n0, 0, K, tid);
    asm volatile("cp.async.commit_group;");
    if (nk > 1) {
        load_stage(smem + STAGE_BYTES, A, P1, P2, m0, n0, 64, K, tid);
        asm volatile("cp.async.commit_group;");
    }

    const int arow = wm * 32 + (lane & 15);
    const int akc = lane >> 4;
    const int bq = lane >> 3;
    const int brow = wn * 16 + ((bq >> 1) << 3) + (lane & 7);
    const int bkc = bq & 1;

    for (int i = 0; i < nk; i++) {
        if (i + 2 < nk) {
            load_stage(smem + ((i + 2) % NSTAGES) * STAGE_BYTES,
                       A, P1, P2, m0, n0, (i + 2) * 64, K, tid);
            asm volatile("cp.async.commit_group;");
        }
        int allow = nk - 1 - i;
        if (allow > 2) { allow = 2; }
        if (allow == 2) {
            asm volatile("cp.async.wait_group 2;");
        } else if (allow == 1) {
            asm volatile("cp.async.wait_group 1;");
        } else {
            asm volatile("cp.async.wait_group 0;");
        }
        __syncthreads();

        float accA[2][2][4];
        float accB[2][2][4];
#pragma unroll
        for (int ii = 0; ii < 2; ii++) {
#pragma unroll
            for (int jj = 0; jj < 2; jj++) {
#pragma unroll
                for (int kk2 = 0; kk2 < 4; kk2++) {
                    accA[ii][jj][kk2] = 0.0f;
                    accB[ii][jj][kk2] = 0.0f;
                }
            }
        }

        uint32_t base = smem + (i % NSTAGES) * STAGE_BYTES;
        uint32_t sA = base;
        uint32_t s1 = base + 8192;
        uint32_t s2 = base + 16384;
#pragma unroll
        for (int kk = 0; kk < 4; kk++) {
            uint32_t af[2][4];
            uint32_t b1[4];
            uint32_t b2[4];
#pragma unroll
            for (int mi = 0; mi < 2; mi++) {
                ldsm4(af[mi], sA + SWZ((arow + mi * 16) * 128 + (kk * 2 + akc) * 16));
            }
            ldsm4(b1, s1 + SWZ(brow * 128 + (kk * 2 + bkc) * 16));
            ldsm4(b2, s2 + SWZ(brow * 128 + (kk * 2 + bkc) * 16));
#pragma unroll
            for (int mi = 0; mi < 2; mi++) {
                mma_f16(accA[mi][0], af[mi], b1);
                mma_f16(accA[mi][1], af[mi], b1 + 2);
                mma_f16(accB[mi][0], af[mi], b2);
                mma_f16(accB[mi][1], af[mi], b2 + 2);
            }
        }

#pragma unroll
        for (int ii = 0; ii < 2; ii++) {
#pragma unroll
            for (int jj = 0; jj < 2; jj++) {
#pragma unroll
                for (int kk2 = 0; kk2 < 4; kk2++) {
                    asum[ii][jj][kk2] += fmaf(accB[ii][jj][kk2], H2INV,
                                              accA[ii][jj][kk2]);
                }
            }
        }
        __syncthreads();
    }

    // epilogue: relu(asum + bias) -> g_cur
#pragma unroll
    for (int mi = 0; mi < 2; mi++) {
        int rbase = m0 + wm * 32 + mi * 16 + (lane >> 2);
#pragma unroll
        for (int nf = 0; nf < 2; nf++) {
            int col = n0 + wn * 16 + nf * 8 + (lane & 3) * 2;
            float bia0 = (col < N_real) ? bias[col] : 0.0f;
            float bia1 = (col + 1 < N_real) ? bias[col + 1] : 0.0f;
#pragma unroll
            for (int h = 0; h < 2; h++) {
                int row = rbase + h * 8;
                float cu0 = fmaxf(asum[mi][nf][h * 2 + 0] + bia0, 0.0f);
                float cu1 = fmaxf(asum[mi][nf][h * 2 + 1] + bia1, 0.0f);
                *reinterpret_cast<float2*>(&g_cur[(size_t)row * N + col]) =
                    make_float2(cu0, cu1);
            }
        }
    }
}

// ------------------------------ host launcher ------------------------------
extern "C" void kernel_launch(void* const* d_in, const int* in_sizes, int n_in,
                              void* d_out, int out_size)
{
    const float* x  = (const float*)d_in[0];
    const float* W1 = (const float*)d_in[1];
    const float* b1 = (const float*)d_in[2];
    const float* W2 = (const float*)d_in[3];
    const float* b2 = (const float*)d_in[4];
    const float* W3 = (const float*)d_in[5];
    const float* b3 = (const float*)d_in[6];
    const float* W4 = (const float*)d_in[7];
    const float* b4 = (const float*)d_in[8];
    const float* W5 = (const float*)d_in[9];
    const float* b5 = (const float*)d_in[10];

    float* out = (float*)d_out;
    float* out_spk = out;
    float* out_mem = out + (size_t)TSTEPS * BATCH * D5;

    static int smem_set = 0;
    if (smem_set == 0) {
        cudaFuncSetAttribute(gemm_kernel,
                             cudaFuncAttributeMaxDynamicSharedMemorySize,
                             NSTAGES * STAGE_BYTES);
        smem_set = 1;
    }

    const int MB = MROWS / 64;   // 800

    // interleaved order: puts gemm launches at indices 3, 6, 9, 12
    cur1_kernel<<<dim3(2, 16), 256>>>(x, W1, b1);                    // 0
    lif1_scan_kernel<<<(BATCH * D1) / 256, 256>>>();                 // 1

    split_w_kernel<<<128, 256>>>(W2, D2, D1, D2, W2OFF);             // 2
    gemm_kernel<<<dim3(D2 / 64, MB), 256, NSTAGES * STAGE_BYTES>>>(  // 3
        0, W2OFF, b2, D2, D2, D1);
    lif_scan_kernel<<<(BATCH * D2) / 1024, 256>>>(1, D2);            // 4

    split_w_kernel<<<256, 256>>>(W3, D3, D2, D3, W3OFF);             // 5
    gemm_kernel<<<dim3(D3 / 64, MB), 256, NSTAGES * STAGE_BYTES>>>(  // 6
        1, W3OFF, b3, D3, D3, D2);
    lif_scan_kernel<<<(BATCH * D3) / 1024, 256>>>(0, D3);            // 7

    split_w_kernel<<<512, 256>>>(W4, D4, D3, D4, W4OFF);             // 8
    gemm_kernel<<<dim3(D4 / 64, MB), 256, NSTAGES * STAGE_BYTES>>>(  // 9
        0, W4OFF, b4, D4, D4, D3);
    lif_scan_kernel<<<(BATCH * D4) / 1024, 256>>>(1, D4);            // 10

    split_w_kernel<<<896, 256>>>(W5, D5, D4, D5P, W5OFF);            // 11
    gemm_kernel<<<dim3(D5P / 64, MB), 256, NSTAGES * STAGE_BYTES>>>( // 12
        1, W5OFF, b5, D5P, D5, D4);
    lif5_scan_kernel<<<(BATCH * D5) / 1024, 256>>>(out_spk, out_mem);// 13
}

// round 14
// speedup vs baseline: 1.1818x; 1.0482x over previous
#include <cuda_runtime.h>
#include <cuda_fp16.h>
#include <stdint.h>
#include <math.h>

#define BATCH 2048
#define TSTEPS 25
#define MROWS (TSTEPS * BATCH)       // 51200
#define D0 100
#define D1 128
#define D2 256
#define D3 512
#define D4 1024
#define D5 784
#define D5P 832

#define BETA 0.95f
#define THRESH 1.0f
#define H2SCALE 2048.0f
#define H2INV (1.0f / 2048.0f)

// ------------------------- persistent device state -------------------------
__device__ float g_cur1[BATCH * D1];

__device__ __half g_spkA[(size_t)MROWS * D4];
__device__ __half g_spkB[(size_t)MROWS * D4];
__device__ float  g_cur[(size_t)MROWS * D4];

#define W2OFF 0
#define W3OFF (W2OFF + D2*D1)
#define W4OFF (W3OFF + D3*D2)
#define W5OFF (W4OFF + D4*D3)
#define WTOTAL (W5OFF + D5P*D4)
__device__ __half g_h1[WTOTAL];
__device__ __half g_h2[WTOTAL];

// ------------------------------ utilities ----------------------------------
__global__ void split_w_kernel(const float* __restrict__ W, int N, int K,
                               int Npad, int off)
{
    int stride = gridDim.x * blockDim.x;
    int total = Npad * K;
    int nk = N * K;
    for (int i = blockIdx.x * blockDim.x + threadIdx.x; i < total; i += stride) {
        float w = 0.0f;
        if (i < nk) { w = W[i]; }
        __half h1 = __float2half(w);
        float r1 = w - __half2float(h1);
        g_h1[off + i] = h1;
        g_h2[off + i] = __float2half(r1 * H2SCALE);
    }
}

__global__ void lif1_scan_kernel()
{
    int idx = blockIdx.x * blockDim.x + threadIdx.x;
    if (idx < BATCH * D1) {
        float cur = g_cur1[idx];
        float mem = 0.0f;
#pragma unroll
        for (int t = 0; t < TSTEPS; t++) {
            float rst = (mem > THRESH) ? 1.0f : 0.0f;
            mem = BETA * mem + cur - rst * THRESH;
            float sp = (mem > THRESH) ? 1.0f : 0.0f;
            g_spkA[(size_t)t * (BATCH * D1) + idx] = __float2half(sp);
        }
    }
}

// LIF scan, 4 elements per thread: g_cur fp32 -> spikes fp16
__global__ void lif_scan_kernel(int sbuf, int N)
{
    __half* spk = (sbuf == 0) ? g_spkA : g_spkB;
    int idx = (blockIdx.x * blockDim.x + threadIdx.x) * 4;
    size_t stride = (size_t)BATCH * N;
    float m0 = 0.0f;
    float m1 = 0.0f;
    float m2 = 0.0f;
    float m3 = 0.0f;
#pragma unroll
    for (int t = 0; t < TSTEPS; t++) {
        float4 cur = *reinterpret_cast<const float4*>(&g_cur[(size_t)t * stride + idx]);
        float r0 = (m0 > THRESH) ? 1.0f : 0.0f;
        float r1 = (m1 > THRESH) ? 1.0f : 0.0f;
        float r2 = (m2 > THRESH) ? 1.0f : 0.0f;
        float r3 = (m3 > THRESH) ? 1.0f : 0.0f;
        m0 = BETA * m0 + cur.x - r0 * THRESH;
        m1 = BETA * m1 + cur.y - r1 * THRESH;
        m2 = BETA * m2 + cur.z - r2 * THRESH;
        m3 = BETA * m3 + cur.w - r3 * THRESH;
        __half2 p0;
        __half2 p1;
        p0.x = __float2half((m0 > THRESH) ? 1.0f : 0.0f);
        p0.y = __float2half((m1 > THRESH) ? 1.0f : 0.0f);
        p1.x = __float2half((m2 > THRESH) ? 1.0f : 0.0f);
        p1.y = __float2half((m3 > THRESH) ? 1.0f : 0.0f);
        uint2 pk;
        pk.x = *reinterpret_cast<uint32_t*>(&p0);
        pk.y = *reinterpret_cast<uint32_t*>(&p1);
        *reinterpret_cast<uint2*>(&spk[(size_t)t * stride + idx]) = pk;
    }
}

// layer-5 scan, 4 elements per thread (784 % 4 == 0 keeps quads in-row)
__global__ void lif5_scan_kernel(float* __restrict__ out_spk,
                                 float* __restrict__ out_mem)
{
    int idx = (blockIdx.x * blockDim.x + threadIdx.x) * 4;
    int b = idx / D5;
    int n = idx - b * D5;
    size_t cbase = (size_t)b * D5P + n;
    size_t cstep = (size_t)BATCH * D5P;
    size_t ostep = (size_t)BATCH * D5;
    float m0 = 0.0f;
    float m1 = 0.0f;
    float m2 = 0.0f;
    float m3 = 0.0f;
#pragma unroll
    for (int t = 0; t < TSTEPS; t++) {
        float4 cur = *reinterpret_cast<const float4*>(&g_cur[cbase + (size_t)t * cstep]);
        float r0 = (m0 > THRESH) ? 1.0f : 0.0f;
        float r1 = (m1 > THRESH) ? 1.0f : 0.0f;
        float r2 = (m2 > THRESH) ? 1.0f : 0.0f;
        float r3 = (m3 > THRESH) ? 1.0f : 0.0f;
        m0 = BETA * m0 + cur.x - r0 * THRESH;
        m1 = BETA * m1 + cur.y - r1 * THRESH;
        m2 = BETA * m2 + cur.z - r2 * THRESH;
        m3 = BETA * m3 + cur.w - r3 * THRESH;
        float4 sp;
        sp.x = (m0 > THRESH) ? 1.0f : 0.0f;
        sp.y = (m1 > THRESH) ? 1.0f : 0.0f;
        sp.z = (m2 > THRESH) ? 1.0f : 0.0f;
        sp.w = (m3 > THRESH) ? 1.0f : 0.0f;
        *reinterpret_cast<float4*>(&out_spk[(size_t)t * ostep + idx]) = sp;
        float4 tm;
        tm.x = tanhf(m0);
        tm.y = tanhf(m1);
        tm.z = tanhf(m2);
        tm.w = tanhf(m3);
        *reinterpret_cast<float4*>(&out_mem[(size_t)t * ostep + idx]) = tm;
    }
}

// ----------------- layer-1 fp32 GEMM (runs once per launch) ----------------
__global__ __launch_bounds__(256)
void cur1_kernel(const float* __restrict__ A, const float* __restrict__ W,
                 const float* __restrict__ bias)
{
    const int N = D1;
    const int K = D0;
    __shared__ float As[16][128];
    __shared__ float Ws[16][64];

    int tid = threadIdx.x;
    int tx = tid & 15;
    int ty = tid >> 4;
    int m0 = blockIdx.y * 128;
    int n0 = blockIdx.x * 64;

    float acc[8][4];
#pragma unroll
    for (int i = 0; i < 8; i++) {
#pragma unroll
        for (int j = 0; j < 4; j++) { acc[i][j] = 0.0f; }
    }

    for (int k0 = 0; k0 < K; k0 += 16) {
#pragma unroll
        for (int it = 0; it < 2; it++) {
            int f4 = it * 256 + tid;
            int row = f4 >> 2;
            int q = f4 & 3;
            int gk = k0 + q * 4;
            float4 v = make_float4(0.f, 0.f, 0.f, 0.f);
            if (gk < K) {
                v = *reinterpret_cast<const float4*>(&A[(size_t)(m0 + row) * K + gk]);
            }
            As[q*4+0][row] = v.x;
            As[q*4+1][row] = v.y;
            As[q*4+2][row] = v.z;
            As[q*4+3][row] = v.w;
        }
        {
            int row = tid >> 2;
            int q = tid & 3;
            int gk = k0 + q * 4;
            float4 v = make_float4(0.f, 0.f, 0.f, 0.f);
            if (gk < K) {
                v = *reinterpret_cast<const float4*>(&W[(size_t)(n0 + row) * K + gk]);
            }
            Ws[q*4+0][row] = v.x;
            Ws[q*4+1][row] = v.y;
            Ws[q*4+2][row] = v.z;
            Ws[q*4+3][row] = v.w;
        }
        __syncthreads();
#pragma unroll
        for (int kk = 0; kk < 16; kk++) {
            float av[8];
            float wv[4];
#pragma unroll
            for (int i = 0; i < 8; i++) { av[i] = As[kk][ty * 8 + i]; }
#pragma unroll
            for (int j = 0; j < 4; j++) { wv[j] = Ws[kk][tx * 4 + j]; }
#pragma unroll
            for (int i = 0; i < 8; i++) {
#pragma unroll
                for (int j = 0; j < 4; j++) {
                    acc[i][j] = fmaf(av[i], wv[j], acc[i][j]);
                }
            }
        }
        __syncthreads();
    }

#pragma unroll
    for (int i = 0; i < 8; i++) {
        int gm = m0 + ty * 8 + i;
#pragma unroll
        for (int j = 0; j < 4; j++) {
            int gn = n0 + tx * 4 + j;
            g_cur1[(size_t)gm * N + gn] = fmaxf(acc[i][j] + bias[gn], 0.0f);
        }
    }
}

// ------------------- tensor-core GEMM (mma.sync, fp16 2-term) --------------
// BM=128, BN=64, BK=64; 8 warps as 4(M) x 2(N); warp tile 32x32; 3 stages.
// Zero-C mma into temp d, immediate fp32 fold -> low register pressure.
#define SWZ(x) ((x) ^ (((x) >> 3) & 0x70))
#define ABUF_BYTES 16384
#define BBUF_BYTES 8192
#define STAGE_BYTES 32768
#define NSTAGES 3

__device__ __forceinline__ void cp16(uint32_t s, const void* g)
{
    asm volatile("cp.async.cg.shared.global [%0], [%1], 16;" :: "r"(s), "l"(g));
}

__device__ __forceinline__ void ldsm4(uint32_t* r, uint32_t s)
{
    asm volatile("ldmatrix.sync.aligned.m8n8.x4.shared.b16 {%0,%1,%2,%3}, [%4];"
                 : "=r"(r[0]), "=r"(r[1]), "=r"(r[2]), "=r"(r[3]) : "r"(s));
}

// D = A*B + 0  (D distinct from C; zero quad is loop-invariant)
__device__ __forceinline__ void mma_f16_z(float* d, const uint32_t* a, const uint32_t* b)
{
    asm volatile("mma.sync.aligned.m16n8k16.row.col.f32.f16.f16.f32 "
                 "{%0,%1,%2,%3}, {%4,%5,%6,%7}, {%8,%9}, {%10,%11,%12,%13};"
                 : "=f"(d[0]), "=f"(d[1]), "=f"(d[2]), "=f"(d[3])
                 : "r"(a[0]), "r"(a[1]), "r"(a[2]), "r"(a[3]),
                   "r"(b[0]), "r"(b[1]),
                   "f"(0.0f), "f"(0.0f), "f"(0.0f), "f"(0.0f));
}

__device__ __forceinline__ void load_stage(uint32_t sbase,
                                           const __half* A, const __half* P1,
                                           const __half* P2,
                                           int m0, int n0, int k0, int K, int tid)
{
    int crow = tid >> 3;
    int ccol = tid & 7;
    // A: 128 rows x 64 halfs (128B/row)
#pragma unroll
    for (int it = 0; it < 4; it++) {
        int row = it * 32 + crow;
        cp16(sbase + SWZ(row * 128 + ccol * 16),
             A + (size_t)(m0 + row) * K + k0 + ccol * 8);
    }
    // B1, B2: 64 rows x 64 halfs each
#pragma unroll
    for (int it = 0; it < 2; it++) {
        int row = it * 32 + crow;
        uint32_t d = SWZ(row * 128 + ccol * 16);
        size_t goff = (size_t)(n0 + row) * K + k0 + ccol * 8;
        cp16(sbase + ABUF_BYTES + d, P1 + goff);
        cp16(sbase + ABUF_BYTES + BBUF_BYTES + d, P2 + goff);
    }
}

// C[M=51200, N] = A[M,K] @ (h1 + h2/2048)[N,K]^T ; relu(+bias) -> g_cur
__global__ __launch_bounds__(256)
void gemm_kernel(int abuf, int woff, const float* __restrict__ bias,
                 int N, int N_real, int K)
{
    extern __shared__ __align__(128) char smem_raw[];
    const uint32_t smem = (uint32_t)__cvta_generic_to_shared(smem_raw);

    const __half* __restrict__ A  = (abuf == 0) ? g_spkA : g_spkB;
    const __half* __restrict__ P1 = g_h1 + woff;
    const __half* __restrict__ P2 = g_h2 + woff;

    const int tid = threadIdx.x;
    const int lane = tid & 31;
    const int warp = tid >> 5;
    const int wm = warp >> 1;           // 0..3  (M direction, 32 rows)
    const int wn = warp & 1;            // 0..1  (N direction, 32 cols)
    const int m0 = blockIdx.y * 128;
    const int n0 = blockIdx.x * 64;

    float asum[2][4][4];
#pragma unroll
    for (int i = 0; i < 2; i++) {
#pragma unroll
        for (int j = 0; j < 4; j++) {
#pragma unroll
            for (int k = 0; k < 4; k++) { asum[i][j][k] = 0.0f; }
        }
    }

    const int nk = K >> 6;

    load_stage(smem, A, P1, P2, m0, n0, 0, K, tid);
    asm volatile("cp.async.commit_group;");
    if (nk > 1) {
        load_stage(smem + STAGE_BYTES, A, P1, P2, m0, n0, 64, K, tid);
        asm volatile("cp.async.commit_group;");
    }

    const int arow = wm * 32 + (lane & 15);
    const int akc = lane >> 4;
    const int bq = lane >> 3;
    const int brow0 = wn * 32 + ((bq >> 1) << 3) + (lane & 7);
    const int bkc = bq & 1;

    for (int i = 0; i < nk; i++) {
        if (i + 2 < nk) {
            load_stage(smem + ((i + 2) % NSTAGES) * STAGE_BYTES,
                       A, P1, P2, m0, n0, (i + 2) * 64, K, tid);
            asm volatile("cp.async.commit_group;");
        }
        int allow = nk - 1 - i;
        if (allow > 2) { allow = 2; }
        if (allow == 2) {
            asm volatile("cp.async.wait_group 2;");
        } else if (allow == 1) {
            asm volatile("cp.async.wait_group 1;");
        } else {
            asm volatile("cp.async.wait_group 0;");
        }
        __syncthreads();

        uint32_t base = smem + (i % NSTAGES) * STAGE_BYTES;
        uint32_t sA = base;
        uint32_t s1 = base + ABUF_BYTES;
        uint32_t s2 = base + ABUF_BYTES + BBUF_BYTES;
#pragma unroll
        for (int kk = 0; kk < 4; kk++) {
            uint32_t af[2][4];
            uint32_t bf[8];
            float d[2][4][4];
#pragma unroll
            for (int mi = 0; mi < 2; mi++) {
                ldsm4(af[mi], sA + SWZ((arow + mi * 16) * 128 + (kk * 2 + akc) * 16));
            }
            // ---- h1 term ----
            ldsm4(bf,     s1 + SWZ(brow0 * 128 + (kk * 2 + bkc) * 16));
            ldsm4(bf + 4, s1 + SWZ((brow0 + 16) * 128 + (kk * 2 + bkc) * 16));
#pragma unroll
            for (int mi = 0; mi < 2; mi++) {
#pragma unroll
                for (int nf = 0; nf < 4; nf++) {
                    mma_f16_z(d[mi][nf], af[mi], bf + 2 * nf);
                }
            }
#pragma unroll
            for (int mi = 0; mi < 2; mi++) {
#pragma unroll
                for (int nf = 0; nf < 4; nf++) {
#pragma unroll
                    for (int e = 0; e < 4; e++) {
                        asum[mi][nf][e] += d[mi][nf][e];
                    }
                }
            }
            // ---- h2 term (reuse b fragments + temp) ----
            ldsm4(bf,     s2 + SWZ(brow0 * 128 + (kk * 2 + bkc) * 16));
            ldsm4(bf + 4, s2 + SWZ((brow0 + 16) * 128 + (kk * 2 + bkc) * 16));
#pragma unroll
            for (int mi = 0; mi < 2; mi++) {
#pragma unroll
                for (int nf = 0; nf < 4; nf++) {
                    mma_f16_z(d[mi][nf], af[mi], bf + 2 * nf);
                }
            }
#pragma unroll
            for (int mi = 0; mi < 2; mi++) {
#pragma unroll
                for (int nf = 0; nf < 4; nf++) {
#pragma unroll
                    for (int e = 0; e < 4; e++) {
                        asum[mi][nf][e] = fmaf(d[mi][nf][e], H2INV, asum[mi][nf][e]);
                    }
                }
            }
        }
        __syncthreads();
    }

    // epilogue: relu(asum + bias) -> g_cur
#pragma unroll
    for (int mi = 0; mi < 2; mi++) {
        int rbase = m0 + wm * 32 + mi * 16 + (lane >> 2);
#pragma unroll
        for (int nf = 0; nf < 4; nf++) {
            int col = n0 + wn * 32 + nf * 8 + (lane & 3) * 2;
            float bia0 = (col < N_real) ? bias[col] : 0.0f;
            float bia1 = (col + 1 < N_real) ? bias[col + 1] : 0.0f;
#pragma unroll
            for (int h = 0; h < 2; h++) {
                int row = rbase + h * 8;
                float cu0 = fmaxf(asum[mi][nf][h * 2 + 0] + bia0, 0.0f);
                float cu1 = fmaxf(asum[mi][nf][h * 2 + 1] + bia1, 0.0f);
                *reinterpret_cast<float2*>(&g_cur[(size_t)row * N + col]) =
                    make_float2(cu0, cu1);
            }
        }
    }
}

// ------------------------------ host launcher ------------------------------
extern "C" void kernel_launch(void* const* d_in, const int* in_sizes, int n_in,
                              void* d_out, int out_size)
{
    const float* x  = (const float*)d_in[0];
    const float* W1 = (const float*)d_in[1];
    const float* b1 = (const float*)d_in[2];
    const float* W2 = (const float*)d_in[3];
    const float* b2 = (const float*)d_in[4];
    const float* W3 = (const float*)d_in[5];
    const float* b3 = (const float*)d_in[6];
    const float* W4 = (const float*)d_in[7];
    const float* b4 = (const float*)d_in[8];
    const float* W5 = (const float*)d_in[9];
    const float* b5 = (const float*)d_in[10];

    float* out = (float*)d_out;
    float* out_spk = out;
    float* out_mem = out + (size_t)TSTEPS * BATCH * D5;

    static int smem_set = 0;
    if (smem_set == 0) {
        cudaFuncSetAttribute(gemm_kernel,
                             cudaFuncAttributeMaxDynamicSharedMemorySize,
                             NSTAGES * STAGE_BYTES);
        smem_set = 1;
    }

    const int MB = MROWS / 128;   // 400

    cur1_kernel<<<dim3(2, 16), 256>>>(x, W1, b1);                    // 0
    lif1_scan_kernel<<<(BATCH * D1) / 256, 256>>>();                 // 1

    split_w_kernel<<<128, 256>>>(W2, D2, D1, D2, W2OFF);             // 2
    gemm_kernel<<<dim3(D2 / 64, MB), 256, NSTAGES * STAGE_BYTES>>>(  // 3
        0, W2OFF, b2, D2, D2, D1);
    lif_scan_kernel<<<(BATCH * D2) / 1024, 256>>>(1, D2);            // 4

    split_w_kernel<<<256, 256>>>(W3, D3, D2, D3, W3OFF);             // 5
    gemm_kernel<<<dim3(D3 / 64, MB), 256, NSTAGES * STAGE_BYTES>>>(  // 6
        1, W3OFF, b3, D3, D3, D2);
    lif_scan_kernel<<<(BATCH * D3) / 1024, 256>>>(0, D3);            // 7

    split_w_kernel<<<512, 256>>>(W4, D4, D3, D4, W4OFF);             // 8
    gemm_kernel<<<dim3(D4 / 64, MB), 256, NSTAGES * STAGE_BYTES>>>(  // 9
        0, W4OFF, b4, D4, D4, D3);
    lif_scan_kernel<<<(BATCH * D4) / 1024, 256>>>(1, D4);            // 10

    split_w_kernel<<<896, 256>>>(W5, D5, D4, D5P, W5OFF);            // 11
    gemm_kernel<<<dim3(D5P / 64, MB), 256, NSTAGES * STAGE_BYTES>>>( // 12
        1, W5OFF, b5, D5P, D5, D4);
    lif5_scan_kernel<<<(BATCH * D5) / 1024, 256>>>(out_spk, out_mem);// 13
}